// round 4
// baseline (speedup 1.0000x reference)
#include <cuda_runtime.h>
#include <math.h>

#define BB 128
#define NN 256
#define MM (BB*NN)
#define KNBR 16
#define BN_SCALE_F 0.99999500003749969f

// ---------------- scratch (device globals; no allocation allowed) ----------
__device__ float g_U[MM * 256];
__device__ float g_V[MM * 256];
__device__ float g_h1[MM * 64];
__device__ float g_h2[MM * 128];
__device__ int   g_idx[MM * KNBR];
__device__ float g_p[BB * 256];
__device__ float g_D2[(size_t)BB * NN * NN];   // 33.5 MB, mostly L2-resident

// ---------------- fused kNN for D=6 (distance math trivial) ----------------
__global__ __launch_bounds__(256, 1)
void knn6_kernel(const float* __restrict__ X, int* __restrict__ idx_out) {
    __shared__ float Xs[NN * 8];
    __shared__ float sqs[NN];
    const int b = blockIdx.x;
    const int t = threadIdx.x;
    const float* Xb = X + (size_t)b * NN * 6;

    for (int e = t; e < NN * 6; e += 256)
        Xs[(e / 6) * 8 + (e % 6)] = Xb[e];
    Xs[t * 8 + 6] = 0.f; Xs[t * 8 + 7] = 0.f;
    __syncthreads();

    float4 xi0 = *reinterpret_cast<const float4*>(&Xs[t * 8]);
    float4 xi1 = *reinterpret_cast<const float4*>(&Xs[t * 8 + 4]);
    float sq = xi0.x*xi0.x + xi0.y*xi0.y + xi0.z*xi0.z + xi0.w*xi0.w
             + xi1.x*xi1.x + xi1.y*xi1.y;
    sqs[t] = sq;
    __syncthreads();

    float bd[KNBR]; int bj[KNBR];
    #pragma unroll
    for (int s = 0; s < KNBR; ++s) { bd[s] = INFINITY; bj[s] = -1; }

    for (int j = 0; j < NN; ++j) {
        float4 v0 = *reinterpret_cast<const float4*>(&Xs[j * 8]);
        float4 v1 = *reinterpret_cast<const float4*>(&Xs[j * 8 + 4]);
        float dot = xi0.x*v0.x + xi0.y*v0.y + xi0.z*v0.z + xi0.w*v0.w
                  + xi1.x*v1.x + xi1.y*v1.y;
        float d2 = sq + sqs[j] - 2.f * dot;
        if (j != t && d2 < bd[KNBR - 1]) {
            float nd = d2; int nj = j;
            #pragma unroll
            for (int s = 0; s < KNBR; ++s) {
                if (nd < bd[s]) {
                    float td = bd[s]; int tj = bj[s];
                    bd[s] = nd; bj[s] = nj; nd = td; nj = tj;
                }
            }
        }
    }
    #pragma unroll
    for (int s = 0; s < KNBR; ++s)
        idx_out[((size_t)b * NN + t) * KNBR + s] = bj[s];
}

// ---------------- distance GEMM (sq fused): d2 = |i|^2+|j|^2-2 X.X^T -------
// Smem pitch 68 floats: 16B-aligned rows for LDS.128, 68%32==4 avoids
// write-bank conflicts among the 4 same-column writer threads.
template<int K>
__global__ __launch_bounds__(256)
void dist_gemm_kernel(const float* __restrict__ X, float* __restrict__ D2) {
    __shared__ float As[16][68];
    __shared__ float Bs[16][68];
    __shared__ float sqa[64], sqb[64];
    const int b = blockIdx.z;
    const int m0 = blockIdx.x * 64, n0 = blockIdx.y * 64;
    const float* Xb = X + (size_t)b * NN * K;
    const int t = threadIdx.x;
    const int tx = t & 15, ty = t >> 4;

    float acc[4][4] = {};
    float sa = 0.f, sb = 0.f;
    for (int k0 = 0; k0 < K; k0 += 16) {
        const int m = t >> 2, kk = (t & 3) * 4;
        float4 av = *reinterpret_cast<const float4*>(&Xb[(size_t)(m0 + m) * K + k0 + kk]);
        float4 bv = *reinterpret_cast<const float4*>(&Xb[(size_t)(n0 + m) * K + k0 + kk]);
        sa += av.x*av.x + av.y*av.y + av.z*av.z + av.w*av.w;
        sb += bv.x*bv.x + bv.y*bv.y + bv.z*bv.z + bv.w*bv.w;
        As[kk + 0][m] = av.x; As[kk + 1][m] = av.y;
        As[kk + 2][m] = av.z; As[kk + 3][m] = av.w;
        Bs[kk + 0][m] = bv.x; Bs[kk + 1][m] = bv.y;
        Bs[kk + 2][m] = bv.z; Bs[kk + 3][m] = bv.w;
        __syncthreads();
        #pragma unroll
        for (int k = 0; k < 16; ++k) {
            float a[4];
            #pragma unroll
            for (int i = 0; i < 4; ++i) a[i] = As[k][ty * 4 + i];
            float4 bq = *reinterpret_cast<float4*>(&Bs[k][tx * 4]);
            #pragma unroll
            for (int i = 0; i < 4; ++i) {
                acc[i][0] += a[i] * bq.x; acc[i][1] += a[i] * bq.y;
                acc[i][2] += a[i] * bq.z; acc[i][3] += a[i] * bq.w;
            }
        }
        __syncthreads();
    }
    // reduce squared norms across the 4 loader lanes of each row (lanes m*4+e)
    sa += __shfl_xor_sync(0xffffffffu, sa, 1);
    sa += __shfl_xor_sync(0xffffffffu, sa, 2);
    sb += __shfl_xor_sync(0xffffffffu, sb, 1);
    sb += __shfl_xor_sync(0xffffffffu, sb, 2);
    if ((t & 3) == 0) { sqa[t >> 2] = sa; sqb[t >> 2] = sb; }
    __syncthreads();

    #pragma unroll
    for (int i = 0; i < 4; ++i) {
        float si = sqa[ty * 4 + i];
        float4 o;
        o.x = si + sqb[tx * 4 + 0] - 2.f * acc[i][0];
        o.y = si + sqb[tx * 4 + 1] - 2.f * acc[i][1];
        o.z = si + sqb[tx * 4 + 2] - 2.f * acc[i][2];
        o.w = si + sqb[tx * 4 + 3] - 2.f * acc[i][3];
        *reinterpret_cast<float4*>(
            &D2[((size_t)b * NN + m0 + ty * 4 + i) * NN + n0 + tx * 4]) = o;
    }
}

// ---------------- top-16: 4-way split scan + stable merge ------------------
__global__ __launch_bounds__(256)
void topk_kernel(const float* __restrict__ D2, int* __restrict__ idx_out) {
    __shared__ float sd[64 * 64];   // [row r][chunk q][slot s]
    __shared__ int   si[64 * 64];
    const int b = blockIdx.x;
    const int i0 = blockIdx.y * 64;
    const int t = threadIdx.x;
    const int r = t >> 2, q = t & 3;
    const int i = i0 + r;
    const float* row = D2 + ((size_t)b * NN + i) * NN + q * 64;

    float bd[KNBR]; int bj[KNBR];
    #pragma unroll
    for (int s = 0; s < KNBR; ++s) { bd[s] = INFINITY; bj[s] = -1; }

    for (int j4 = 0; j4 < 16; ++j4) {
        float4 v = *reinterpret_cast<const float4*>(&row[j4 * 4]);
        float dv[4] = {v.x, v.y, v.z, v.w};
        #pragma unroll
        for (int e = 0; e < 4; ++e) {
            int j = q * 64 + j4 * 4 + e;
            float d2 = dv[e];
            if (j != i && d2 < bd[KNBR - 1]) {
                float nd = d2; int nj = j;
                #pragma unroll
                for (int s = 0; s < KNBR; ++s) {
                    if (nd < bd[s]) {
                        float td = bd[s]; int tj = bj[s];
                        bd[s] = nd; bj[s] = nj; nd = td; nj = tj;
                    }
                }
            }
        }
    }
    #pragma unroll
    for (int s = 0; s < KNBR; ++s) {
        sd[(r * 4 + q) * 16 + s] = bd[s];
        si[(r * 4 + q) * 16 + s] = bj[s];
    }
    __syncthreads();

    if (q == 0) {
        float fd[KNBR]; int fj[KNBR];
        #pragma unroll
        for (int s = 0; s < KNBR; ++s) { fd[s] = INFINITY; fj[s] = -1; }
        // chunks in ascending index order, each sorted ascending (stable);
        // strict < insert keeps the lower-index candidate on ties.
        for (int qq = 0; qq < 4; ++qq) {
            for (int s = 0; s < KNBR; ++s) {
                float d = sd[(r * 4 + qq) * 16 + s];
                if (!(d < fd[KNBR - 1])) break;   // rest of chunk is >= this
                int nj = si[(r * 4 + qq) * 16 + s];
                float nd = d;
                #pragma unroll
                for (int s2 = 0; s2 < KNBR; ++s2) {
                    if (nd < fd[s2]) {
                        float td = fd[s2]; int tj = fj[s2];
                        fd[s2] = nd; fj[s2] = nj; nd = td; nj = tj;
                    }
                }
            }
        }
        #pragma unroll
        for (int s = 0; s < KNBR; ++s)
            idx_out[((size_t)b * NN + i) * KNBR + s] = fj[s];
    }
}

// ---------------- layer-1 U/V GEMM (K=6, C=64): tiny, direct ---------------
__global__ __launch_bounds__(256)
void uv_gemm1_kernel(const float* __restrict__ X, const float* __restrict__ W,
                     float* __restrict__ U, float* __restrict__ V) {
    __shared__ float Ws[12][64];
    int t = threadIdx.x;
    for (int e = t; e < 12 * 64; e += 256) Ws[e / 64][e % 64] = W[e];
    __syncthreads();
    int m = blockIdx.x * 4 + (t >> 6);
    int c = t & 63;
    const float* x = X + (size_t)m * 6;
    float u = 0.f, v = 0.f;
    #pragma unroll
    for (int d = 0; d < 6; ++d) {
        float xd = x[d];
        u += xd * Ws[d][c];
        v += xd * Ws[6 + d][c];
    }
    U[(size_t)m * 64 + c] = u;
    V[(size_t)m * 64 + c] = v;
}

// ---------------- generic U/V GEMM: BM=64 BN=64 BK=16, 4x4/thread ----------
template<int K, int C>
__global__ __launch_bounds__(256)
void uv_gemm_kernel(const float* __restrict__ X, const float* __restrict__ W,
                    float* __restrict__ U, float* __restrict__ V) {
    __shared__ float As[16][68];
    __shared__ float Wt[16][64];
    __shared__ float Wb[16][64];
    const int t = threadIdx.x;
    const int m0 = blockIdx.x * 64;
    const int n0 = blockIdx.y * 64;
    const int tx = t & 15, ty = t >> 4;

    float accU[4][4] = {}, accV[4][4] = {};

    for (int k0 = 0; k0 < K; k0 += 16) {
        {
            int m = t >> 2;
            int kk = (t & 3) * 4;
            float4 xv = *reinterpret_cast<const float4*>(&X[(size_t)(m0 + m) * K + k0 + kk]);
            As[kk + 0][m] = xv.x; As[kk + 1][m] = xv.y;
            As[kk + 2][m] = xv.z; As[kk + 3][m] = xv.w;
        }
        {
            int k  = t >> 4;
            int nn = (t & 15) * 4;
            float4 wt = *reinterpret_cast<const float4*>(&W[(size_t)(k0 + k) * C + n0 + nn]);
            float4 wb = *reinterpret_cast<const float4*>(&W[(size_t)(K + k0 + k) * C + n0 + nn]);
            *reinterpret_cast<float4*>(&Wt[k][nn]) = wt;
            *reinterpret_cast<float4*>(&Wb[k][nn]) = wb;
        }
        __syncthreads();
        #pragma unroll
        for (int k = 0; k < 16; ++k) {
            float a[4];
            #pragma unroll
            for (int i = 0; i < 4; ++i) a[i] = As[k][ty * 4 + i];
            float4 wt = *reinterpret_cast<float4*>(&Wt[k][tx * 4]);
            float4 wb = *reinterpret_cast<float4*>(&Wb[k][tx * 4]);
            #pragma unroll
            for (int i = 0; i < 4; ++i) {
                accU[i][0] += a[i] * wt.x; accU[i][1] += a[i] * wt.y;
                accU[i][2] += a[i] * wt.z; accU[i][3] += a[i] * wt.w;
                accV[i][0] += a[i] * wb.x; accV[i][1] += a[i] * wb.y;
                accV[i][2] += a[i] * wb.z; accV[i][3] += a[i] * wb.w;
            }
        }
        __syncthreads();
    }
    #pragma unroll
    for (int i = 0; i < 4; ++i) {
        float4 ou = make_float4(accU[i][0], accU[i][1], accU[i][2], accU[i][3]);
        float4 ov = make_float4(accV[i][0], accV[i][1], accV[i][2], accV[i][3]);
        *reinterpret_cast<float4*>(&U[(size_t)(m0 + ty * 4 + i) * C + n0 + tx * 4]) = ou;
        *reinterpret_cast<float4*>(&V[(size_t)(m0 + ty * 4 + i) * C + n0 + tx * 4]) = ov;
    }
}

// ------- smem-slab aggregation: V batch slab cached in shared --------------
// CH = channels held in slab (full C, or C/2 split across blockIdx.y).
template<int C, int CH>
__global__ __launch_bounds__(256)
void agg_slab_kernel(const float* __restrict__ U, const float* __restrict__ V,
                     const int* __restrict__ idx, const float* __restrict__ bias,
                     const float* __restrict__ g, const float* __restrict__ be,
                     float* __restrict__ H) {
    extern __shared__ float Vs[];            // [256][CH]
    __shared__ int sidx[NN * KNBR];
    const int b = blockIdx.x;
    const int c0 = blockIdx.y * CH;
    const int t = threadIdx.x;
    const float* Vb = V + (size_t)b * NN * C + c0;

    constexpr int RQ = CH / 4;
    for (int e = t; e < NN * RQ; e += 256) {
        int row = e / RQ, qq = e % RQ;
        *reinterpret_cast<float4*>(&Vs[row * CH + qq * 4]) =
            *reinterpret_cast<const float4*>(&Vb[(size_t)row * C + qq * 4]);
    }
    for (int e = t; e < NN * KNBR; e += 256)
        sidx[e] = idx[(size_t)b * NN * KNBR + e];
    __syncthreads();

    constexpr int PP = 256 / CH;
    const int lp = t / CH, cl = t % CH, c = c0 + cl;
    const float a  = g[c] * BN_SCALE_F;
    const float bi = bias[c], bee = be[c];

    for (int p0 = 0; p0 < NN; p0 += PP) {
        const int pt = p0 + lp;
        const int gp = b * NN + pt;
        float u = U[(size_t)gp * C + c];
        float v = Vs[pt * CH + cl];
        float mx = -INFINITY, mn = INFINITY;
        #pragma unroll
        for (int k = 0; k < KNBR; ++k) {
            float val = Vs[sidx[pt * KNBR + k] * CH + cl];
            mx = fmaxf(mx, val);
            mn = fminf(mn, val);
        }
        float m = (a >= 0.f) ? mx : mn;
        H[(size_t)gp * C + c] = fmaxf(fmaf(a, u - v + m + bi, bee), 0.f);
    }
}

// ------- layer-3: slab aggregation fused with global max pool (h >= 0) -----
template<int C, int CH>
__global__ __launch_bounds__(256)
void agg_slab_pool_kernel(const float* __restrict__ U, const float* __restrict__ V,
                          const int* __restrict__ idx, const float* __restrict__ bias,
                          const float* __restrict__ g, const float* __restrict__ be,
                          int* __restrict__ P) {
    extern __shared__ float Vs[];            // [256][CH]
    __shared__ int sidx[NN * KNBR];
    const int b = blockIdx.x;
    const int c0 = blockIdx.y * CH;
    const int t = threadIdx.x;
    const float* Vb = V + (size_t)b * NN * C + c0;

    constexpr int RQ = CH / 4;
    for (int e = t; e < NN * RQ; e += 256) {
        int row = e / RQ, qq = e % RQ;
        *reinterpret_cast<float4*>(&Vs[row * CH + qq * 4]) =
            *reinterpret_cast<const float4*>(&Vb[(size_t)row * C + qq * 4]);
    }
    for (int e = t; e < NN * KNBR; e += 256)
        sidx[e] = idx[(size_t)b * NN * KNBR + e];
    __syncthreads();

    constexpr int PP = 256 / CH;
    const int lp = t / CH, cl = t % CH, c = c0 + cl;
    const float a  = g[c] * BN_SCALE_F;
    const float bi = bias[c], bee = be[c];

    float pool = 0.f;   // h >= 0
    for (int p0 = 0; p0 < NN; p0 += PP) {
        const int pt = p0 + lp;
        const int gp = b * NN + pt;
        float u = U[(size_t)gp * C + c];
        float v = Vs[pt * CH + cl];
        float mx = -INFINITY, mn = INFINITY;
        #pragma unroll
        for (int k = 0; k < KNBR; ++k) {
            float val = Vs[sidx[pt * KNBR + k] * CH + cl];
            mx = fmaxf(mx, val);
            mn = fminf(mn, val);
        }
        float m = (a >= 0.f) ? mx : mn;
        pool = fmaxf(pool, fmaf(a, u - v + m + bi, bee));
    }
    // non-negative floats: int-compare == float-compare
    atomicMax(&P[b * C + c], __float_as_int(pool));
}

// ---------------- FC head --------------------------------------------------
__global__ __launch_bounds__(256)
void head_kernel(const float* __restrict__ Pp, const float* __restrict__ Wf1,
                 const float* __restrict__ bf1, const float* __restrict__ gf,
                 const float* __restrict__ bef, const float* __restrict__ Wf2,
                 const float* __restrict__ bf2, float* __restrict__ out) {
    __shared__ float ps[256];
    __shared__ float fs[128];
    const int b = blockIdx.x, t = threadIdx.x;
    ps[t] = Pp[b * 256 + t];
    __syncthreads();
    if (t < 128) {
        float acc = bf1[t];
        for (int r = 0; r < 256; ++r) acc += ps[r] * Wf1[r * 128 + t];
        float a = gf[t] * BN_SCALE_F;
        fs[t] = fmaxf(fmaf(a, acc, bef[t]), 0.f);
    }
    __syncthreads();
    if (t < 12) {
        float acc = bf2[t];
        for (int j = 0; j < 128; ++j) acc += fs[j] * Wf2[j * 12 + t];
        out[b * 12 + t] = acc;
    }
}

// ---------------- launch ----------------------------------------------------
extern "C" void kernel_launch(void* const* d_in, const int* in_sizes, int n_in,
                              void* d_out, int out_size) {
    const float* x   = (const float*)d_in[0];
    const float* W1  = (const float*)d_in[1];
    const float* b1  = (const float*)d_in[2];
    const float* g1  = (const float*)d_in[3];
    const float* be1 = (const float*)d_in[4];
    const float* W2  = (const float*)d_in[5];
    const float* b2  = (const float*)d_in[6];
    const float* g2  = (const float*)d_in[7];
    const float* be2 = (const float*)d_in[8];
    const float* W3  = (const float*)d_in[9];
    const float* b3  = (const float*)d_in[10];
    const float* g3  = (const float*)d_in[11];
    const float* be3 = (const float*)d_in[12];
    const float* Wf1 = (const float*)d_in[13];
    const float* bf1 = (const float*)d_in[14];
    const float* gf  = (const float*)d_in[15];
    const float* bef = (const float*)d_in[16];
    const float* Wf2 = (const float*)d_in[17];
    const float* bf2 = (const float*)d_in[18];
    float* out = (float*)d_out;

    float *U, *V, *h1, *h2, *p, *D2;
    int* idx;
    cudaGetSymbolAddress((void**)&U,  g_U);
    cudaGetSymbolAddress((void**)&V,  g_V);
    cudaGetSymbolAddress((void**)&h1, g_h1);
    cudaGetSymbolAddress((void**)&h2, g_h2);
    cudaGetSymbolAddress((void**)&idx, g_idx);
    cudaGetSymbolAddress((void**)&p,  g_p);
    cudaGetSymbolAddress((void**)&D2, g_D2);

    const int slab64  = NN * 64  * 4;   //  64 KB
    const int slab128 = NN * 128 * 4;   // 128 KB
    cudaFuncSetAttribute(agg_slab_kernel<64, 64>,
                         cudaFuncAttributeMaxDynamicSharedMemorySize, slab64);
    cudaFuncSetAttribute(agg_slab_kernel<128, 128>,
                         cudaFuncAttributeMaxDynamicSharedMemorySize, slab128);
    cudaFuncSetAttribute(agg_slab_pool_kernel<256, 128>,
                         cudaFuncAttributeMaxDynamicSharedMemorySize, slab128);

    // ---- layer 1: D=6 -> C=64 ----
    knn6_kernel<<<BB, 256>>>(x, idx);
    uv_gemm1_kernel<<<MM / 4, 256>>>(x, W1, U, V);
    agg_slab_kernel<64, 64><<<BB, 256, slab64>>>(U, V, idx, b1, g1, be1, h1);

    // ---- layer 2: D=64 -> C=128 ----
    dist_gemm_kernel<64><<<dim3(4, 4, BB), 256>>>(h1, D2);
    topk_kernel<<<dim3(BB, 4), 256>>>(D2, idx);
    uv_gemm_kernel<64, 128><<<dim3(MM / 64, 2), 256>>>(h1, W2, U, V);
    agg_slab_kernel<128, 128><<<BB, 256, slab128>>>(U, V, idx, b2, g2, be2, h2);

    // ---- layer 3: D=128 -> C=256 ----
    dist_gemm_kernel<128><<<dim3(4, 4, BB), 256>>>(h2, D2);
    topk_kernel<<<dim3(BB, 4), 256>>>(D2, idx);
    uv_gemm_kernel<128, 256><<<dim3(MM / 64, 4), 256>>>(h2, W3, U, V);
    cudaMemsetAsync(p, 0, BB * 256 * sizeof(float));
    agg_slab_pool_kernel<256, 128><<<dim3(BB, 2), 256, slab128>>>(
        U, V, idx, b3, g3, be3, (int*)p);

    // ---- head ----
    head_kernel<<<BB, 256>>>(p, Wf1, bf1, gf, bef, Wf2, bf2, out);
}

// round 5
// speedup vs baseline: 1.0016x; 1.0016x over previous
#include <cuda_runtime.h>
#include <math.h>

#define BB 128
#define NN 256
#define MM (BB*NN)
#define KNBR 16
#define BN_SCALE_F 0.99999500003749969f

// ---------------- scratch (device globals; no allocation allowed) ----------
__device__ float g_U[MM * 256];
__device__ float g_V[MM * 256];
__device__ float g_h1[MM * 64];
__device__ float g_h2[MM * 128];
__device__ int   g_idx[MM * KNBR];
__device__ float g_p[BB * 256];
__device__ float g_xp[MM * 8];          // layer-1 input padded 6 -> 8

// ---------------- pad x (B,N,6) -> (B,N,8) ---------------------------------
__global__ __launch_bounds__(256)
void pad_kernel(const float* __restrict__ x, float* __restrict__ xp) {
    const int m = blockIdx.x * 256 + threadIdx.x;
    const float* s = x + (size_t)m * 6;
    float4 o0 = make_float4(s[0], s[1], s[2], s[3]);
    float4 o1 = make_float4(s[4], s[5], 0.f, 0.f);
    *reinterpret_cast<float4*>(&xp[(size_t)m * 8])     = o0;
    *reinterpret_cast<float4*>(&xp[(size_t)m * 8 + 4]) = o1;
}

// ============ fused kNN: dist GEMM + top-16, all in one block ==============
// Block: 64-row m-tile x all 256 cols of one batch. 256 threads.
// Bs stages the full 256-col k-chunk (A-rows are a subset of it).
// d2 tile (64x256) lives in dynamic smem; top-16 via 4-way split scan +
// stable ascending merge (preserves lax.top_k lower-index tie-break).
template<int K>
__global__ __launch_bounds__(256)
void knn_fused_kernel(const float* __restrict__ X, int* __restrict__ idx_out) {
    __shared__ float Bs[8][260];
    __shared__ float sqb[256];
    extern __shared__ float D2s[];          // [64][260]
    const int b  = blockIdx.y;
    const int m0 = blockIdx.x * 64;         // batch-local row offset
    const int t  = threadIdx.x;
    const float* Xb = X + (size_t)b * NN * K;

    const int tn = t & 31, tm = t >> 5;     // cols tn*4 & 128+tn*4, rows tm*8..+7
    float acc[8][8] = {};
    float snorm = 0.f;

    for (int k0 = 0; k0 < K; k0 += 8) {
        float4 v0 = *reinterpret_cast<const float4*>(&Xb[(size_t)t * K + k0]);
        float4 v1 = *reinterpret_cast<const float4*>(&Xb[(size_t)t * K + k0 + 4]);
        snorm += v0.x*v0.x + v0.y*v0.y + v0.z*v0.z + v0.w*v0.w
               + v1.x*v1.x + v1.y*v1.y + v1.z*v1.z + v1.w*v1.w;
        Bs[0][t] = v0.x; Bs[1][t] = v0.y; Bs[2][t] = v0.z; Bs[3][t] = v0.w;
        Bs[4][t] = v1.x; Bs[5][t] = v1.y; Bs[6][t] = v1.z; Bs[7][t] = v1.w;
        __syncthreads();
        #pragma unroll
        for (int k = 0; k < 8; ++k) {
            float4 a0 = *reinterpret_cast<const float4*>(&Bs[k][m0 + tm * 8]);
            float4 a1 = *reinterpret_cast<const float4*>(&Bs[k][m0 + tm * 8 + 4]);
            float4 b0 = *reinterpret_cast<const float4*>(&Bs[k][tn * 4]);
            float4 b1 = *reinterpret_cast<const float4*>(&Bs[k][128 + tn * 4]);
            float av[8] = {a0.x, a0.y, a0.z, a0.w, a1.x, a1.y, a1.z, a1.w};
            float bv[8] = {b0.x, b0.y, b0.z, b0.w, b1.x, b1.y, b1.z, b1.w};
            #pragma unroll
            for (int i = 0; i < 8; ++i) {
                #pragma unroll
                for (int c = 0; c < 8; ++c)
                    acc[i][c] += av[i] * bv[c];
            }
        }
        __syncthreads();
    }
    sqb[t] = snorm;
    __syncthreads();

    // epilogue: d2 = |i|^2 + |j|^2 - 2 dot -> smem tile
    #pragma unroll
    for (int i = 0; i < 8; ++i) {
        const int row = tm * 8 + i;              // local row
        const float si = sqb[m0 + row];
        float4 o0, o1;
        o0.x = si + sqb[tn*4+0]     - 2.f * acc[i][0];
        o0.y = si + sqb[tn*4+1]     - 2.f * acc[i][1];
        o0.z = si + sqb[tn*4+2]     - 2.f * acc[i][2];
        o0.w = si + sqb[tn*4+3]     - 2.f * acc[i][3];
        o1.x = si + sqb[128+tn*4+0] - 2.f * acc[i][4];
        o1.y = si + sqb[128+tn*4+1] - 2.f * acc[i][5];
        o1.z = si + sqb[128+tn*4+2] - 2.f * acc[i][6];
        o1.w = si + sqb[128+tn*4+3] - 2.f * acc[i][7];
        *reinterpret_cast<float4*>(&D2s[row * 260 + tn * 4])       = o0;
        *reinterpret_cast<float4*>(&D2s[row * 260 + 128 + tn * 4]) = o1;
    }
    __syncthreads();

    // ---- top-16: 4 threads per row scan contiguous 64-col chunks ----
    const int r = t >> 2, q = t & 3;
    const int i_self = m0 + r;                   // batch-local self index
    float bd[KNBR]; int bj[KNBR];
    #pragma unroll
    for (int s = 0; s < KNBR; ++s) { bd[s] = INFINITY; bj[s] = -1; }

    for (int j4 = 0; j4 < 16; ++j4) {
        float4 v = *reinterpret_cast<const float4*>(&D2s[r * 260 + q * 64 + j4 * 4]);
        float dv[4] = {v.x, v.y, v.z, v.w};
        #pragma unroll
        for (int e = 0; e < 4; ++e) {
            const int j = q * 64 + j4 * 4 + e;
            const float d2 = dv[e];
            if (j != i_self && d2 < bd[KNBR - 1]) {
                float nd = d2; int nj = j;
                #pragma unroll
                for (int s = 0; s < KNBR; ++s) {
                    if (nd < bd[s]) {
                        float td = bd[s]; int tj = bj[s];
                        bd[s] = nd; bj[s] = nj; nd = td; nj = tj;
                    }
                }
            }
        }
    }
    __syncthreads();                             // all scans done; reuse D2s
    float* sd = D2s;                             // [64*4][16]
    int*   si = reinterpret_cast<int*>(D2s + 4096);
    #pragma unroll
    for (int s = 0; s < KNBR; ++s) {
        sd[(r * 4 + q) * 16 + s] = bd[s];
        si[(r * 4 + q) * 16 + s] = bj[s];
    }
    __syncthreads();

    if (q == 0) {
        float fd[KNBR]; int fj[KNBR];
        #pragma unroll
        for (int s = 0; s < KNBR; ++s) { fd[s] = INFINITY; fj[s] = -1; }
        // ascending chunk order, each list sorted ascending; strict < insert
        // keeps the lower-index candidate on exact ties.
        for (int qq = 0; qq < 4; ++qq) {
            for (int s = 0; s < KNBR; ++s) {
                float d = sd[(r * 4 + qq) * 16 + s];
                if (!(d < fd[KNBR - 1])) break;
                int nj = si[(r * 4 + qq) * 16 + s];
                float nd = d;
                #pragma unroll
                for (int s2 = 0; s2 < KNBR; ++s2) {
                    if (nd < fd[s2]) {
                        float td = fd[s2]; int tj = fj[s2];
                        fd[s2] = nd; fj[s2] = nj; nd = td; nj = tj;
                    }
                }
            }
        }
        #pragma unroll
        for (int s = 0; s < KNBR; ++s)
            idx_out[((size_t)b * NN + m0 + r) * KNBR + s] = fj[s];
    }
}

// ---------------- layer-1 U/V GEMM (K=6, C=64): tiny, direct ---------------
__global__ __launch_bounds__(256)
void uv_gemm1_kernel(const float* __restrict__ X, const float* __restrict__ W,
                     float* __restrict__ U, float* __restrict__ V) {
    __shared__ float Ws[12][64];
    int t = threadIdx.x;
    for (int e = t; e < 12 * 64; e += 256) Ws[e / 64][e % 64] = W[e];
    __syncthreads();
    int m = blockIdx.x * 4 + (t >> 6);
    int c = t & 63;
    const float* x = X + (size_t)m * 6;
    float u = 0.f, v = 0.f;
    #pragma unroll
    for (int d = 0; d < 6; ++d) {
        float xd = x[d];
        u += xd * Ws[d][c];
        v += xd * Ws[6 + d][c];
    }
    U[(size_t)m * 64 + c] = u;
    V[(size_t)m * 64 + c] = v;
}

// ---------------- generic U/V GEMM: BM=64 BN=64 BK=16, 4x4/thread ----------
template<int K, int C>
__global__ __launch_bounds__(256)
void uv_gemm_kernel(const float* __restrict__ X, const float* __restrict__ W,
                    float* __restrict__ U, float* __restrict__ V) {
    __shared__ float As[16][68];
    __shared__ float Wt[16][64];
    __shared__ float Wb[16][64];
    const int t = threadIdx.x;
    const int m0 = blockIdx.x * 64;
    const int n0 = blockIdx.y * 64;
    const int tx = t & 15, ty = t >> 4;

    float accU[4][4] = {}, accV[4][4] = {};

    for (int k0 = 0; k0 < K; k0 += 16) {
        {
            int m = t >> 2;
            int kk = (t & 3) * 4;
            float4 xv = *reinterpret_cast<const float4*>(&X[(size_t)(m0 + m) * K + k0 + kk]);
            As[kk + 0][m] = xv.x; As[kk + 1][m] = xv.y;
            As[kk + 2][m] = xv.z; As[kk + 3][m] = xv.w;
        }
        {
            int k  = t >> 4;
            int nn = (t & 15) * 4;
            float4 wt = *reinterpret_cast<const float4*>(&W[(size_t)(k0 + k) * C + n0 + nn]);
            float4 wb = *reinterpret_cast<const float4*>(&W[(size_t)(K + k0 + k) * C + n0 + nn]);
            *reinterpret_cast<float4*>(&Wt[k][nn]) = wt;
            *reinterpret_cast<float4*>(&Wb[k][nn]) = wb;
        }
        __syncthreads();
        #pragma unroll
        for (int k = 0; k < 16; ++k) {
            float a[4];
            #pragma unroll
            for (int i = 0; i < 4; ++i) a[i] = As[k][ty * 4 + i];
            float4 wt = *reinterpret_cast<float4*>(&Wt[k][tx * 4]);
            float4 wb = *reinterpret_cast<float4*>(&Wb[k][tx * 4]);
            #pragma unroll
            for (int i = 0; i < 4; ++i) {
                accU[i][0] += a[i] * wt.x; accU[i][1] += a[i] * wt.y;
                accU[i][2] += a[i] * wt.z; accU[i][3] += a[i] * wt.w;
                accV[i][0] += a[i] * wb.x; accV[i][1] += a[i] * wb.y;
                accV[i][2] += a[i] * wb.z; accV[i][3] += a[i] * wb.w;
            }
        }
        __syncthreads();
    }
    #pragma unroll
    for (int i = 0; i < 4; ++i) {
        float4 ou = make_float4(accU[i][0], accU[i][1], accU[i][2], accU[i][3]);
        float4 ov = make_float4(accV[i][0], accV[i][1], accV[i][2], accV[i][3]);
        *reinterpret_cast<float4*>(&U[(size_t)(m0 + ty * 4 + i) * C + n0 + tx * 4]) = ou;
        *reinterpret_cast<float4*>(&V[(size_t)(m0 + ty * 4 + i) * C + n0 + tx * 4]) = ov;
    }
}

// ---------------- neighbor aggregation + BN + ReLU (high-grid) -------------
template<int C>
__global__ __launch_bounds__(256)
void agg_kernel(const float* __restrict__ U, const float* __restrict__ V,
                const int* __restrict__ idx, const float* __restrict__ bias,
                const float* __restrict__ g, const float* __restrict__ be,
                float* __restrict__ H) {
    constexpr int PPB = 256 / C;
    __shared__ int sidx[PPB * KNBR];
    const int p0 = blockIdx.x * PPB;
    const int t = threadIdx.x;
    if (t < PPB * KNBR) sidx[t] = idx[(size_t)p0 * KNBR + t];
    __syncthreads();
    const int lp = t / C, c = t % C;
    const int pt = p0 + lp;
    const int b = pt >> 8;
    const float* Vb = V + ((size_t)(b << 8)) * C;
    float u = U[(size_t)pt * C + c];
    float v = V[(size_t)pt * C + c];
    float mx = -INFINITY, mn = INFINITY;
    #pragma unroll
    for (int k = 0; k < KNBR; ++k) {
        float val = Vb[(size_t)sidx[lp * KNBR + k] * C + c];
        mx = fmaxf(mx, val);
        mn = fminf(mn, val);
    }
    float a = g[c] * BN_SCALE_F;
    float m = (a >= 0.f) ? mx : mn;
    float h = fmaf(a, u - v + m + bias[c], be[c]);
    H[(size_t)pt * C + c] = fmaxf(h, 0.f);
}

// ------- layer-3 aggregation fused with global max pool (h >= 0) -----------
template<int C>
__global__ __launch_bounds__(256)
void agg_pool_kernel(const float* __restrict__ U, const float* __restrict__ V,
                     const int* __restrict__ idx, const float* __restrict__ bias,
                     const float* __restrict__ g, const float* __restrict__ be,
                     int* __restrict__ P) {
    __shared__ int sidx[KNBR];
    const int pt = blockIdx.x;
    const int t = threadIdx.x;
    if (t < KNBR) sidx[t] = idx[(size_t)pt * KNBR + t];
    __syncthreads();
    const int c = t;
    const int b = pt >> 8;
    const float* Vb = V + ((size_t)(b << 8)) * C;
    float u = U[(size_t)pt * C + c];
    float v = V[(size_t)pt * C + c];
    float mx = -INFINITY, mn = INFINITY;
    #pragma unroll
    for (int k = 0; k < KNBR; ++k) {
        float val = Vb[(size_t)sidx[k] * C + c];
        mx = fmaxf(mx, val);
        mn = fminf(mn, val);
    }
    float a = g[c] * BN_SCALE_F;
    float m = (a >= 0.f) ? mx : mn;
    float h = fmaxf(fmaf(a, u - v + m + bias[c], be[c]), 0.f);
    // h >= 0: int compare == float compare; pool via atomicMax
    atomicMax(&P[b * C + c], __float_as_int(h));
}

// ---------------- FC head --------------------------------------------------
__global__ __launch_bounds__(256)
void head_kernel(const float* __restrict__ Pp, const float* __restrict__ Wf1,
                 const float* __restrict__ bf1, const float* __restrict__ gf,
                 const float* __restrict__ bef, const float* __restrict__ Wf2,
                 const float* __restrict__ bf2, float* __restrict__ out) {
    __shared__ float ps[256];
    __shared__ float fs[128];
    const int b = blockIdx.x, t = threadIdx.x;
    ps[t] = Pp[b * 256 + t];
    __syncthreads();
    if (t < 128) {
        float acc = bf1[t];
        for (int r = 0; r < 256; ++r) acc += ps[r] * Wf1[r * 128 + t];
        float a = gf[t] * BN_SCALE_F;
        fs[t] = fmaxf(fmaf(a, acc, bef[t]), 0.f);
    }
    __syncthreads();
    if (t < 12) {
        float acc = bf2[t];
        for (int j = 0; j < 128; ++j) acc += fs[j] * Wf2[j * 12 + t];
        out[b * 12 + t] = acc;
    }
}

// ---------------- launch ----------------------------------------------------
extern "C" void kernel_launch(void* const* d_in, const int* in_sizes, int n_in,
                              void* d_out, int out_size) {
    const float* x   = (const float*)d_in[0];
    const float* W1  = (const float*)d_in[1];
    const float* b1  = (const float*)d_in[2];
    const float* g1  = (const float*)d_in[3];
    const float* be1 = (const float*)d_in[4];
    const float* W2  = (const float*)d_in[5];
    const float* b2  = (const float*)d_in[6];
    const float* g2  = (const float*)d_in[7];
    const float* be2 = (const float*)d_in[8];
    const float* W3  = (const float*)d_in[9];
    const float* b3  = (const float*)d_in[10];
    const float* g3  = (const float*)d_in[11];
    const float* be3 = (const float*)d_in[12];
    const float* Wf1 = (const float*)d_in[13];
    const float* bf1 = (const float*)d_in[14];
    const float* gf  = (const float*)d_in[15];
    const float* bef = (const float*)d_in[16];
    const float* Wf2 = (const float*)d_in[17];
    const float* bf2 = (const float*)d_in[18];
    float* out = (float*)d_out;

    float *U, *V, *h1, *h2, *p, *xp;
    int* idx;
    cudaGetSymbolAddress((void**)&U,  g_U);
    cudaGetSymbolAddress((void**)&V,  g_V);
    cudaGetSymbolAddress((void**)&h1, g_h1);
    cudaGetSymbolAddress((void**)&h2, g_h2);
    cudaGetSymbolAddress((void**)&idx, g_idx);
    cudaGetSymbolAddress((void**)&p,  g_p);
    cudaGetSymbolAddress((void**)&xp, g_xp);

    const int d2smem = 64 * 260 * 4;   // 66,560 B dynamic
    cudaFuncSetAttribute(knn_fused_kernel<8>,
                         cudaFuncAttributeMaxDynamicSharedMemorySize, d2smem);
    cudaFuncSetAttribute(knn_fused_kernel<64>,
                         cudaFuncAttributeMaxDynamicSharedMemorySize, d2smem);
    cudaFuncSetAttribute(knn_fused_kernel<128>,
                         cudaFuncAttributeMaxDynamicSharedMemorySize, d2smem);

    // ---- layer 1: D=6 -> C=64 ----
    pad_kernel<<<MM / 256, 256>>>(x, xp);
    knn_fused_kernel<8><<<dim3(4, BB), 256, d2smem>>>(xp, idx);
    uv_gemm1_kernel<<<MM / 4, 256>>>(x, W1, U, V);
    agg_kernel<64><<<MM / 4, 256>>>(U, V, idx, b1, g1, be1, h1);

    // ---- layer 2: D=64 -> C=128 ----
    knn_fused_kernel<64><<<dim3(4, BB), 256, d2smem>>>(h1, idx);
    uv_gemm_kernel<64, 128><<<dim3(MM / 64, 2), 256>>>(h1, W2, U, V);
    agg_kernel<128><<<MM / 2, 256>>>(U, V, idx, b2, g2, be2, h2);

    // ---- layer 3: D=128 -> C=256 ----
    knn_fused_kernel<128><<<dim3(4, BB), 256, d2smem>>>(h2, idx);
    uv_gemm_kernel<128, 256><<<dim3(MM / 64, 4), 256>>>(h2, W3, U, V);
    cudaMemsetAsync(p, 0, BB * 256 * sizeof(float));
    agg_pool_kernel<256><<<MM, 256>>>(U, V, idx, b3, g3, be3, (int*)p);

    // ---- head ----
    head_kernel<<<BB, 256>>>(p, Wf1, bf1, gf, bef, Wf2, bf2, out);
}

// round 6
// speedup vs baseline: 1.0035x; 1.0020x over previous
#include <cuda_runtime.h>
#include <math.h>

#define BB 128
#define NN 256
#define MM (BB*NN)
#define KNBR 16
#define BN_SCALE_F 0.99999500003749969f

// ---------------- scratch (device globals; no allocation allowed) ----------
__device__ float g_U[MM * 256];
__device__ float g_V[MM * 256];
__device__ float g_h1[MM * 64];
__device__ float g_h2[MM * 128];
__device__ int   g_idx[MM * KNBR];
__device__ float g_p[BB * 256];

// ============ fused kNN: dist GEMM + top-16, one block per 64-row tile =====
// Double-buffered Bs; D2 tile in dynamic smem; 4-way split scan + stable
// ascending merge (preserves lax.top_k lower-index tie-break).
template<int K, bool PAD6>
__global__ __launch_bounds__(256)
void knn_fused_kernel(const float* __restrict__ X, int* __restrict__ idx_out) {
    __shared__ float Bs[2][8][260];
    __shared__ float sqb[256];
    extern __shared__ float D2s[];          // [64][260]
    const int b  = blockIdx.y;
    const int m0 = blockIdx.x * 64;
    const int t  = threadIdx.x;
    const int KS = PAD6 ? 6 : K;
    const float* Xb = X + (size_t)b * NN * KS;
    const int tn = t & 31, tm = t >> 5;

    float acc[8][8] = {};
    float snorm = 0.f;

    auto load_chunk = [&](int k0, float4& a, float4& c) {
        if (PAD6) {
            const float* s = Xb + t * 6;
            float2 p0 = *reinterpret_cast<const float2*>(s);
            float2 p1 = *reinterpret_cast<const float2*>(s + 2);
            float2 p2 = *reinterpret_cast<const float2*>(s + 4);
            a = make_float4(p0.x, p0.y, p1.x, p1.y);
            c = make_float4(p2.x, p2.y, 0.f, 0.f);
        } else {
            a = *reinterpret_cast<const float4*>(&Xb[(size_t)t * K + k0]);
            c = *reinterpret_cast<const float4*>(&Xb[(size_t)t * K + k0 + 4]);
        }
    };
    auto stage = [&](int buf, const float4& a, const float4& c) {
        Bs[buf][0][t] = a.x; Bs[buf][1][t] = a.y;
        Bs[buf][2][t] = a.z; Bs[buf][3][t] = a.w;
        Bs[buf][4][t] = c.x; Bs[buf][5][t] = c.y;
        Bs[buf][6][t] = c.z; Bs[buf][7][t] = c.w;
    };
    auto compute = [&](int pb) {
        #pragma unroll
        for (int k = 0; k < 8; ++k) {
            float4 a0 = *reinterpret_cast<const float4*>(&Bs[pb][k][m0 + tm * 8]);
            float4 a1 = *reinterpret_cast<const float4*>(&Bs[pb][k][m0 + tm * 8 + 4]);
            float4 b0 = *reinterpret_cast<const float4*>(&Bs[pb][k][tn * 4]);
            float4 b1 = *reinterpret_cast<const float4*>(&Bs[pb][k][128 + tn * 4]);
            float av[8] = {a0.x, a0.y, a0.z, a0.w, a1.x, a1.y, a1.z, a1.w};
            float bv[8] = {b0.x, b0.y, b0.z, b0.w, b1.x, b1.y, b1.z, b1.w};
            #pragma unroll
            for (int i = 0; i < 8; ++i) {
                #pragma unroll
                for (int c = 0; c < 8; ++c)
                    acc[i][c] += av[i] * bv[c];
            }
        }
    };

    float4 v0, v1;
    load_chunk(0, v0, v1);
    snorm += v0.x*v0.x + v0.y*v0.y + v0.z*v0.z + v0.w*v0.w
           + v1.x*v1.x + v1.y*v1.y + v1.z*v1.z + v1.w*v1.w;
    stage(0, v0, v1);
    __syncthreads();

    const int NCH = PAD6 ? 1 : K / 8;
    for (int ci = 1; ci < NCH; ++ci) {
        float4 n0_, n1_;
        load_chunk(ci * 8, n0_, n1_);
        compute((ci - 1) & 1);
        snorm += n0_.x*n0_.x + n0_.y*n0_.y + n0_.z*n0_.z + n0_.w*n0_.w
               + n1_.x*n1_.x + n1_.y*n1_.y + n1_.z*n1_.z + n1_.w*n1_.w;
        stage(ci & 1, n0_, n1_);
        __syncthreads();
    }
    compute((NCH - 1) & 1);
    sqb[t] = snorm;
    __syncthreads();

    // epilogue: d2 = |i|^2 + |j|^2 - 2 dot -> smem tile
    #pragma unroll
    for (int i = 0; i < 8; ++i) {
        const int row = tm * 8 + i;
        const float si = sqb[m0 + row];
        float4 o0, o1;
        o0.x = si + sqb[tn*4+0]     - 2.f * acc[i][0];
        o0.y = si + sqb[tn*4+1]     - 2.f * acc[i][1];
        o0.z = si + sqb[tn*4+2]     - 2.f * acc[i][2];
        o0.w = si + sqb[tn*4+3]     - 2.f * acc[i][3];
        o1.x = si + sqb[128+tn*4+0] - 2.f * acc[i][4];
        o1.y = si + sqb[128+tn*4+1] - 2.f * acc[i][5];
        o1.z = si + sqb[128+tn*4+2] - 2.f * acc[i][6];
        o1.w = si + sqb[128+tn*4+3] - 2.f * acc[i][7];
        *reinterpret_cast<float4*>(&D2s[row * 260 + tn * 4])       = o0;
        *reinterpret_cast<float4*>(&D2s[row * 260 + 128 + tn * 4]) = o1;
    }
    __syncthreads();

    // ---- top-16: 4 threads per row, contiguous 64-col chunks ----
    const int r = t >> 2, q = t & 3;
    const int i_self = m0 + r;
    float bd[KNBR]; int bj[KNBR];
    #pragma unroll
    for (int s = 0; s < KNBR; ++s) { bd[s] = INFINITY; bj[s] = -1; }

    for (int j4 = 0; j4 < 16; ++j4) {
        float4 v = *reinterpret_cast<const float4*>(&D2s[r * 260 + q * 64 + j4 * 4]);
        float dv[4] = {v.x, v.y, v.z, v.w};
        #pragma unroll
        for (int e = 0; e < 4; ++e) {
            const int j = q * 64 + j4 * 4 + e;
            const float d2 = dv[e];
            if (j != i_self && d2 < bd[KNBR - 1]) {
                float nd = d2; int nj = j;
                #pragma unroll
                for (int s = 0; s < KNBR; ++s) {
                    if (nd < bd[s]) {
                        float td = bd[s]; int tj = bj[s];
                        bd[s] = nd; bj[s] = nj; nd = td; nj = tj;
                    }
                }
            }
        }
    }
    __syncthreads();                             // reuse D2s for lists
    float* sd = D2s;
    int*   si = reinterpret_cast<int*>(D2s + 4096);
    #pragma unroll
    for (int s = 0; s < KNBR; ++s) {
        sd[(r * 4 + q) * 16 + s] = bd[s];
        si[(r * 4 + q) * 16 + s] = bj[s];
    }
    __syncthreads();

    if (q == 0) {
        float fd[KNBR]; int fj[KNBR];
        #pragma unroll
        for (int s = 0; s < KNBR; ++s) { fd[s] = INFINITY; fj[s] = -1; }
        for (int qq = 0; qq < 4; ++qq) {
            for (int s = 0; s < KNBR; ++s) {
                float d = sd[(r * 4 + qq) * 16 + s];
                if (!(d < fd[KNBR - 1])) break;
                int nj = si[(r * 4 + qq) * 16 + s];
                float nd = d;
                #pragma unroll
                for (int s2 = 0; s2 < KNBR; ++s2) {
                    if (nd < fd[s2]) {
                        float td = fd[s2]; int tj = fj[s2];
                        fd[s2] = nd; fj[s2] = nj; nd = td; nj = tj;
                    }
                }
            }
        }
        #pragma unroll
        for (int s = 0; s < KNBR; ++s)
            idx_out[((size_t)b * NN + m0 + r) * KNBR + s] = fj[s];
    }
}

// ---------------- layer-1 U/V GEMM (K=6, C=64): tiny, direct ---------------
__global__ __launch_bounds__(256)
void uv_gemm1_kernel(const float* __restrict__ X, const float* __restrict__ W,
                     float* __restrict__ U, float* __restrict__ V) {
    __shared__ float Ws[12][64];
    int t = threadIdx.x;
    for (int e = t; e < 12 * 64; e += 256) Ws[e / 64][e % 64] = W[e];
    __syncthreads();
    int m = blockIdx.x * 4 + (t >> 6);
    int c = t & 63;
    const float* x = X + (size_t)m * 6;
    float u = 0.f, v = 0.f;
    #pragma unroll
    for (int d = 0; d < 6; ++d) {
        float xd = x[d];
        u += xd * Ws[d][c];
        v += xd * Ws[6 + d][c];
    }
    U[(size_t)m * 64 + c] = u;
    V[(size_t)m * 64 + c] = v;
}

// ---- U/V GEMM: BM=128 BN=128 BK=8, 8x8/thread, double-buffered ------------
// grid.y in [0, 2*C/128): first C/128 tiles -> U, rest -> V (W row offset K).
template<int K>
__global__ __launch_bounds__(256)
void uv_gemm8_kernel(const float* __restrict__ X, const float* __restrict__ W,
                     const int C, float* __restrict__ U, float* __restrict__ V) {
    __shared__ float As[2][8][132];
    __shared__ float Wt[2][8][132];
    const int t = threadIdx.x;
    const int m0 = blockIdx.x * 128;
    const int nt = C / 128;
    const bool isU = (int)blockIdx.y < nt;
    const int n0 = (isU ? blockIdx.y : blockIdx.y - nt) * 128;
    const float* Wb = W + (isU ? (size_t)0 : (size_t)K * C);
    float* Out = isU ? U : V;

    const int am = t >> 1, ak = (t & 1) * 4;      // A loader
    const int wk = t >> 5, wn = (t & 31) * 4;     // W loader
    const int tx = t & 15, ty = t >> 4;           // compute tile

    float acc[8][8] = {};

    auto stage = [&](int buf, const float4& xa, const float4& wa) {
        As[buf][ak + 0][am] = xa.x; As[buf][ak + 1][am] = xa.y;
        As[buf][ak + 2][am] = xa.z; As[buf][ak + 3][am] = xa.w;
        *reinterpret_cast<float4*>(&Wt[buf][wk][wn]) = wa;
    };
    auto compute = [&](int pb) {
        #pragma unroll
        for (int k = 0; k < 8; ++k) {
            float4 a0 = *reinterpret_cast<const float4*>(&As[pb][k][ty * 8]);
            float4 a1 = *reinterpret_cast<const float4*>(&As[pb][k][ty * 8 + 4]);
            float4 b0 = *reinterpret_cast<const float4*>(&Wt[pb][k][tx * 4]);
            float4 b1 = *reinterpret_cast<const float4*>(&Wt[pb][k][64 + tx * 4]);
            float av[8] = {a0.x, a0.y, a0.z, a0.w, a1.x, a1.y, a1.z, a1.w};
            float bv[8] = {b0.x, b0.y, b0.z, b0.w, b1.x, b1.y, b1.z, b1.w};
            #pragma unroll
            for (int i = 0; i < 8; ++i) {
                #pragma unroll
                for (int c = 0; c < 8; ++c)
                    acc[i][c] += av[i] * bv[c];
            }
        }
    };

    float4 xa = *reinterpret_cast<const float4*>(&X[(size_t)(m0 + am) * K + ak]);
    float4 wa = *reinterpret_cast<const float4*>(&Wb[(size_t)wk * C + n0 + wn]);
    stage(0, xa, wa);
    __syncthreads();

    const int NCH = K / 8;
    for (int ci = 1; ci < NCH; ++ci) {
        float4 xn = *reinterpret_cast<const float4*>(
            &X[(size_t)(m0 + am) * K + ci * 8 + ak]);
        float4 wnx = *reinterpret_cast<const float4*>(
            &Wb[(size_t)(ci * 8 + wk) * C + n0 + wn]);
        compute((ci - 1) & 1);
        stage(ci & 1, xn, wnx);
        __syncthreads();
    }
    compute((NCH - 1) & 1);

    #pragma unroll
    for (int i = 0; i < 8; ++i) {
        float* dst = &Out[(size_t)(m0 + ty * 8 + i) * C + n0 + tx * 4];
        *reinterpret_cast<float4*>(dst) =
            make_float4(acc[i][0], acc[i][1], acc[i][2], acc[i][3]);
        *reinterpret_cast<float4*>(dst + 64) =
            make_float4(acc[i][4], acc[i][5], acc[i][6], acc[i][7]);
    }
}

// ---------------- neighbor aggregation + BN + ReLU (32-bit offsets) --------
template<int C>
__global__ __launch_bounds__(256)
void agg_kernel(const float* __restrict__ U, const float* __restrict__ V,
                const int* __restrict__ idx, const float* __restrict__ bias,
                const float* __restrict__ g, const float* __restrict__ be,
                float* __restrict__ H) {
    constexpr int PPB = 256 / C;
    __shared__ int sidx[PPB * KNBR];          // element offsets within batch slab
    const int p0 = blockIdx.x * PPB;
    const int t = threadIdx.x;
    if (t < PPB * KNBR) sidx[t] = idx[(size_t)p0 * KNBR + t] * C;
    __syncthreads();
    const int lp = t / C, c = t % C;
    const int pt = p0 + lp;
    const int b = pt >> 8;
    const float* VbC = V + ((size_t)(b << 8)) * C + c;
    float u = U[(size_t)pt * C + c];
    float v = V[(size_t)pt * C + c];
    float mx = -INFINITY, mn = INFINITY;
    #pragma unroll
    for (int k = 0; k < KNBR; ++k) {
        float val = VbC[sidx[lp * KNBR + k]];
        mx = fmaxf(mx, val);
        mn = fminf(mn, val);
    }
    float a = g[c] * BN_SCALE_F;
    float m = (a >= 0.f) ? mx : mn;
    float h = fmaf(a, u - v + m + bias[c], be[c]);
    H[(size_t)pt * C + c] = fmaxf(h, 0.f);
}

// ------- layer-3 aggregation fused with global max pool (h >= 0) -----------
template<int C>
__global__ __launch_bounds__(256)
void agg_pool_kernel(const float* __restrict__ U, const float* __restrict__ V,
                     const int* __restrict__ idx, const float* __restrict__ bias,
                     const float* __restrict__ g, const float* __restrict__ be,
                     int* __restrict__ P) {
    __shared__ int sidx[KNBR];
    const int pt = blockIdx.x;
    const int t = threadIdx.x;
    if (t < KNBR) sidx[t] = idx[(size_t)pt * KNBR + t] * C;
    __syncthreads();
    const int c = t;
    const int b = pt >> 8;
    const float* VbC = V + ((size_t)(b << 8)) * C + c;
    float u = U[(size_t)pt * C + c];
    float v = V[(size_t)pt * C + c];
    float mx = -INFINITY, mn = INFINITY;
    #pragma unroll
    for (int k = 0; k < KNBR; ++k) {
        float val = VbC[sidx[k]];
        mx = fmaxf(mx, val);
        mn = fminf(mn, val);
    }
    float a = g[c] * BN_SCALE_F;
    float m = (a >= 0.f) ? mx : mn;
    float h = fmaxf(fmaf(a, u - v + m + bias[c], be[c]), 0.f);
    atomicMax(&P[b * C + c], __float_as_int(h));   // h >= 0: int cmp == float cmp
}

// ---------------- FC head --------------------------------------------------
__global__ __launch_bounds__(256)
void head_kernel(const float* __restrict__ Pp, const float* __restrict__ Wf1,
                 const float* __restrict__ bf1, const float* __restrict__ gf,
                 const float* __restrict__ bef, const float* __restrict__ Wf2,
                 const float* __restrict__ bf2, float* __restrict__ out) {
    __shared__ float ps[256];
    __shared__ float fs[128];
    const int b = blockIdx.x, t = threadIdx.x;
    ps[t] = Pp[b * 256 + t];
    __syncthreads();
    if (t < 128) {
        float acc = bf1[t];
        for (int r = 0; r < 256; ++r) acc += ps[r] * Wf1[r * 128 + t];
        float a = gf[t] * BN_SCALE_F;
        fs[t] = fmaxf(fmaf(a, acc, bef[t]), 0.f);
    }
    __syncthreads();
    if (t < 12) {
        float acc = bf2[t];
        for (int j = 0; j < 128; ++j) acc += fs[j] * Wf2[j * 12 + t];
        out[b * 12 + t] = acc;
    }
}

// ---------------- launch ----------------------------------------------------
extern "C" void kernel_launch(void* const* d_in, const int* in_sizes, int n_in,
                              void* d_out, int out_size) {
    const float* x   = (const float*)d_in[0];
    const float* W1  = (const float*)d_in[1];
    const float* b1  = (const float*)d_in[2];
    const float* g1  = (const float*)d_in[3];
    const float* be1 = (const float*)d_in[4];
    const float* W2  = (const float*)d_in[5];
    const float* b2  = (const float*)d_in[6];
    const float* g2  = (const float*)d_in[7];
    const float* be2 = (const float*)d_in[8];
    const float* W3  = (const float*)d_in[9];
    const float* b3  = (const float*)d_in[10];
    const float* g3  = (const float*)d_in[11];
    const float* be3 = (const float*)d_in[12];
    const float* Wf1 = (const float*)d_in[13];
    const float* bf1 = (const float*)d_in[14];
    const float* gf  = (const float*)d_in[15];
    const float* bef = (const float*)d_in[16];
    const float* Wf2 = (const float*)d_in[17];
    const float* bf2 = (const float*)d_in[18];
    float* out = (float*)d_out;

    float *U, *V, *h1, *h2, *p;
    int* idx;
    cudaGetSymbolAddress((void**)&U,  g_U);
    cudaGetSymbolAddress((void**)&V,  g_V);
    cudaGetSymbolAddress((void**)&h1, g_h1);
    cudaGetSymbolAddress((void**)&h2, g_h2);
    cudaGetSymbolAddress((void**)&idx, g_idx);
    cudaGetSymbolAddress((void**)&p,  g_p);

    const int d2smem = 64 * 260 * 4;   // 66,560 B dynamic
    cudaFuncSetAttribute(knn_fused_kernel<8, true>,
                         cudaFuncAttributeMaxDynamicSharedMemorySize, d2smem);
    cudaFuncSetAttribute(knn_fused_kernel<64, false>,
                         cudaFuncAttributeMaxDynamicSharedMemorySize, d2smem);
    cudaFuncSetAttribute(knn_fused_kernel<128, false>,
                         cudaFuncAttributeMaxDynamicSharedMemorySize, d2smem);

    // ---- layer 1: D=6 -> C=64 ----
    knn_fused_kernel<8, true><<<dim3(4, BB), 256, d2smem>>>(x, idx);
    uv_gemm1_kernel<<<MM / 4, 256>>>(x, W1, U, V);
    agg_kernel<64><<<MM / 4, 256>>>(U, V, idx, b1, g1, be1, h1);

    // ---- layer 2: D=64 -> C=128 ----
    knn_fused_kernel<64, false><<<dim3(4, BB), 256, d2smem>>>(h1, idx);
    uv_gemm8_kernel<64><<<dim3(MM / 128, 2), 256>>>(h1, W2, 128, U, V);
    agg_kernel<128><<<MM / 2, 256>>>(U, V, idx, b2, g2, be2, h2);

    // ---- layer 3: D=128 -> C=256 ----
    knn_fused_kernel<128, false><<<dim3(4, BB), 256, d2smem>>>(h2, idx);
    uv_gemm8_kernel<128><<<dim3(MM / 128, 4), 256>>>(h2, W3, 256, U, V);
    cudaMemsetAsync(p, 0, BB * 256 * sizeof(float));
    agg_pool_kernel<256><<<MM, 256>>>(U, V, idx, b3, g3, be3, (int*)p);

    // ---- head ----
    head_kernel<<<BB, 256>>>(p, Wf1, bf1, gf, bef, Wf2, bf2, out);
}

// round 8
// speedup vs baseline: 1.1152x; 1.1112x over previous
#include <cuda_runtime.h>
#include <math.h>

#define BB 128
#define NN 256
#define MM (BB*NN)
#define KNBR 16
#define BN_SCALE_F 0.99999500003749969f

// ---------------- scratch (device globals; no allocation allowed) ----------
__device__ float g_U[MM * 256];
__device__ float g_V[MM * 256];
__device__ float g_h1[MM * 64];
__device__ float g_h2[MM * 128];
__device__ int   g_idx[MM * KNBR];
__device__ float g_p[BB * 256];

// Dynamic smem budget (floats): knn needs 2*2080 (Bs dbl) + 256 (sqb) + 16640 (D2s)
#define FAT_SMEM_FLOATS 21056
#define FAT_SMEM_BYTES  (FAT_SMEM_FLOATS * 4)   // 84224

// ============ kNN body: dist GEMM + top-16 (one 64-row tile per block) =====
template<int K, bool PAD6>
__device__ __forceinline__ void knn_body(const float* __restrict__ X,
                                         int* __restrict__ idx_out,
                                         int bid, float* sm) {
    float* BsD = sm;              // [2][8][260]
    float* sqb = sm + 4160;       // [256]
    float* D2s = sm + 4416;       // [64][260]
    const int b  = bid >> 2;
    const int m0 = (bid & 3) * 64;
    const int t  = threadIdx.x;
    const int KS = PAD6 ? 6 : K;
    const float* Xb = X + (size_t)b * NN * KS;
    const int tn = t & 31, tm = t >> 5;

    float acc[8][8] = {};
    float snorm = 0.f;

    auto load_chunk = [&](int k0, float4& a, float4& c) {
        if (PAD6) {
            const float* s = Xb + t * 6;
            float2 p0 = *reinterpret_cast<const float2*>(s);
            float2 p1 = *reinterpret_cast<const float2*>(s + 2);
            float2 p2 = *reinterpret_cast<const float2*>(s + 4);
            a = make_float4(p0.x, p0.y, p1.x, p1.y);
            c = make_float4(p2.x, p2.y, 0.f, 0.f);
        } else {
            a = *reinterpret_cast<const float4*>(&Xb[(size_t)t * K + k0]);
            c = *reinterpret_cast<const float4*>(&Xb[(size_t)t * K + k0 + 4]);
        }
    };
    auto stage = [&](int buf, const float4& a, const float4& c) {
        float* B = BsD + buf * 2080;
        B[0 * 260 + t] = a.x; B[1 * 260 + t] = a.y;
        B[2 * 260 + t] = a.z; B[3 * 260 + t] = a.w;
        B[4 * 260 + t] = c.x; B[5 * 260 + t] = c.y;
        B[6 * 260 + t] = c.z; B[7 * 260 + t] = c.w;
    };
    auto compute = [&](int pb) {
        const float* B = BsD + pb * 2080;
        #pragma unroll
        for (int k = 0; k < 8; ++k) {
            float4 a0 = *reinterpret_cast<const float4*>(&B[k * 260 + m0 + tm * 8]);
            float4 a1 = *reinterpret_cast<const float4*>(&B[k * 260 + m0 + tm * 8 + 4]);
            float4 b0 = *reinterpret_cast<const float4*>(&B[k * 260 + tn * 4]);
            float4 b1 = *reinterpret_cast<const float4*>(&B[k * 260 + 128 + tn * 4]);
            float av[8] = {a0.x, a0.y, a0.z, a0.w, a1.x, a1.y, a1.z, a1.w};
            float bv[8] = {b0.x, b0.y, b0.z, b0.w, b1.x, b1.y, b1.z, b1.w};
            #pragma unroll
            for (int i = 0; i < 8; ++i) {
                #pragma unroll
                for (int c = 0; c < 8; ++c)
                    acc[i][c] += av[i] * bv[c];
            }
        }
    };

    float4 v0, v1;
    load_chunk(0, v0, v1);
    snorm += v0.x*v0.x + v0.y*v0.y + v0.z*v0.z + v0.w*v0.w
           + v1.x*v1.x + v1.y*v1.y + v1.z*v1.z + v1.w*v1.w;
    stage(0, v0, v1);
    __syncthreads();

    const int NCH = PAD6 ? 1 : K / 8;
    for (int ci = 1; ci < NCH; ++ci) {
        float4 n0_, n1_;
        load_chunk(ci * 8, n0_, n1_);
        compute((ci - 1) & 1);
        snorm += n0_.x*n0_.x + n0_.y*n0_.y + n0_.z*n0_.z + n0_.w*n0_.w
               + n1_.x*n1_.x + n1_.y*n1_.y + n1_.z*n1_.z + n1_.w*n1_.w;
        stage(ci & 1, n0_, n1_);
        __syncthreads();
    }
    compute((NCH - 1) & 1);
    sqb[t] = snorm;
    __syncthreads();

    // epilogue: d2 = |i|^2 + |j|^2 - 2 dot -> smem tile
    #pragma unroll
    for (int i = 0; i < 8; ++i) {
        const int row = tm * 8 + i;
        const float si = sqb[m0 + row];
        float4 o0, o1;
        o0.x = si + sqb[tn*4+0]     - 2.f * acc[i][0];
        o0.y = si + sqb[tn*4+1]     - 2.f * acc[i][1];
        o0.z = si + sqb[tn*4+2]     - 2.f * acc[i][2];
        o0.w = si + sqb[tn*4+3]     - 2.f * acc[i][3];
        o1.x = si + sqb[128+tn*4+0] - 2.f * acc[i][4];
        o1.y = si + sqb[128+tn*4+1] - 2.f * acc[i][5];
        o1.z = si + sqb[128+tn*4+2] - 2.f * acc[i][6];
        o1.w = si + sqb[128+tn*4+3] - 2.f * acc[i][7];
        *reinterpret_cast<float4*>(&D2s[row * 260 + tn * 4])       = o0;
        *reinterpret_cast<float4*>(&D2s[row * 260 + 128 + tn * 4]) = o1;
    }
    __syncthreads();

    // poison self-distance so scans need no j != i check
    if (t < 64) D2s[t * 260 + m0 + t] = INFINITY;
    __syncthreads();

    // ---- top-16: 4 threads per row, contiguous 64-col chunks ----
    const int r = t >> 2, q = t & 3;
    float bd[KNBR]; int bj[KNBR];
    #pragma unroll
    for (int s = 0; s < KNBR; ++s) { bd[s] = INFINITY; bj[s] = -1; }

    for (int j4 = 0; j4 < 16; ++j4) {
        float4 v = *reinterpret_cast<const float4*>(&D2s[r * 260 + q * 64 + j4 * 4]);
        float dv[4] = {v.x, v.y, v.z, v.w};
        #pragma unroll
        for (int e = 0; e < 4; ++e) {
            const float d2 = dv[e];
            if (d2 < bd[KNBR - 1]) {
                const int j = q * 64 + j4 * 4 + e;
                float nd = d2; int nj = j;
                #pragma unroll
                for (int s = 0; s < KNBR; ++s) {
                    if (nd < bd[s]) {
                        float td = bd[s]; int tj = bj[s];
                        bd[s] = nd; bj[s] = nj; nd = td; nj = tj;
                    }
                }
            }
        }
    }
    __syncthreads();                             // reuse D2s for lists
    float* sd = D2s;
    int*   si = reinterpret_cast<int*>(D2s + 4096);
    #pragma unroll
    for (int s = 0; s < KNBR; ++s) {
        sd[(r * 4 + q) * 16 + s] = bd[s];
        si[(r * 4 + q) * 16 + s] = bj[s];
    }
    __syncthreads();

    if (q == 0) {
        float fd[KNBR]; int fj[KNBR];
        #pragma unroll
        for (int s = 0; s < KNBR; ++s) { fd[s] = INFINITY; fj[s] = -1; }
        // ascending chunk order, each sorted ascending; strict < insert keeps
        // the lower-index candidate on exact ties (lax.top_k semantics).
        for (int qq = 0; qq < 4; ++qq) {
            for (int s = 0; s < KNBR; ++s) {
                float d = sd[(r * 4 + qq) * 16 + s];
                if (!(d < fd[KNBR - 1])) break;
                int nj = si[(r * 4 + qq) * 16 + s];
                float nd = d;
                #pragma unroll
                for (int s2 = 0; s2 < KNBR; ++s2) {
                    if (nd < fd[s2]) {
                        float td = fd[s2]; int tj = fj[s2];
                        fd[s2] = nd; fj[s2] = nj; nd = td; nj = tj;
                    }
                }
            }
        }
        #pragma unroll
        for (int s = 0; s < KNBR; ++s)
            idx_out[((size_t)b * NN + m0 + r) * KNBR + s] = fj[s];
    }
}

// ---------------- layer-1 U/V body (K=6, C=64): 32 points per block --------
__device__ __forceinline__ void uv1_body(const float* __restrict__ X,
                                         const float* __restrict__ W,
                                         float* __restrict__ U,
                                         float* __restrict__ V,
                                         int bid2, float* sm) {
    float* Ws = sm;                 // [12][64]
    const int t = threadIdx.x;
    for (int e = t; e < 12 * 64; e += 256) Ws[e] = W[e];
    __syncthreads();
    const int c = t & 63, pp = t >> 6;
    const int m0 = bid2 * 32;
    #pragma unroll
    for (int i = 0; i < 8; ++i) {
        const int m = m0 + i * 4 + pp;
        const float* x = X + (size_t)m * 6;
        float u = 0.f, v = 0.f;
        #pragma unroll
        for (int d = 0; d < 6; ++d) {
            float xd = x[d];
            u += xd * Ws[d * 64 + c];
            v += xd * Ws[(6 + d) * 64 + c];
        }
        U[(size_t)m * 64 + c] = u;
        V[(size_t)m * 64 + c] = v;
    }
}

// ---- U/V GEMM body: BM=128 BN=128 BK=8, 8x8/thread, double-buffered -------
template<int K>
__device__ __forceinline__ void uv_body8(const float* __restrict__ X,
                                         const float* __restrict__ W,
                                         const int C, float* __restrict__ U,
                                         float* __restrict__ V,
                                         int bx, int by, float* sm) {
    float* As = sm;                 // [2][8][132]
    float* Wt = sm + 2112;          // [2][8][132]
    const int t = threadIdx.x;
    const int m0 = bx * 128;
    const int nt = C / 128;
    const bool isU = by < nt;
    const int n0 = (isU ? by : by - nt) * 128;
    const float* Wb = W + (isU ? (size_t)0 : (size_t)K * C);
    float* Out = isU ? U : V;

    const int am = t >> 1, ak = (t & 1) * 4;
    const int wk = t >> 5, wn = (t & 31) * 4;
    const int tx = t & 15, ty = t >> 4;

    float acc[8][8] = {};

    auto stage = [&](int buf, const float4& xa, const float4& wa) {
        float* A = As + buf * 1056;
        A[(ak + 0) * 132 + am] = xa.x; A[(ak + 1) * 132 + am] = xa.y;
        A[(ak + 2) * 132 + am] = xa.z; A[(ak + 3) * 132 + am] = xa.w;
        *reinterpret_cast<float4*>(&Wt[buf * 1056 + wk * 132 + wn]) = wa;
    };
    auto compute = [&](int pb) {
        const float* A = As + pb * 1056;
        const float* Wp = Wt + pb * 1056;
        #pragma unroll
        for (int k = 0; k < 8; ++k) {
            float4 a0 = *reinterpret_cast<const float4*>(&A[k * 132 + ty * 8]);
            float4 a1 = *reinterpret_cast<const float4*>(&A[k * 132 + ty * 8 + 4]);
            float4 b0 = *reinterpret_cast<const float4*>(&Wp[k * 132 + tx * 4]);
            float4 b1 = *reinterpret_cast<const float4*>(&Wp[k * 132 + 64 + tx * 4]);
            float av[8] = {a0.x, a0.y, a0.z, a0.w, a1.x, a1.y, a1.z, a1.w};
            float bv[8] = {b0.x, b0.y, b0.z, b0.w, b1.x, b1.y, b1.z, b1.w};
            #pragma unroll
            for (int i = 0; i < 8; ++i) {
                #pragma unroll
                for (int c = 0; c < 8; ++c)
                    acc[i][c] += av[i] * bv[c];
            }
        }
    };

    float4 xa = *reinterpret_cast<const float4*>(&X[(size_t)(m0 + am) * K + ak]);
    float4 wa = *reinterpret_cast<const float4*>(&Wb[(size_t)wk * C + n0 + wn]);
    stage(0, xa, wa);
    __syncthreads();

    const int NCH = K / 8;
    for (int ci = 1; ci < NCH; ++ci) {
        float4 xn = *reinterpret_cast<const float4*>(
            &X[(size_t)(m0 + am) * K + ci * 8 + ak]);
        float4 wnx = *reinterpret_cast<const float4*>(
            &Wb[(size_t)(ci * 8 + wk) * C + n0 + wn]);
        compute((ci - 1) & 1);
        stage(ci & 1, xn, wnx);
        __syncthreads();
    }
    compute((NCH - 1) & 1);

    #pragma unroll
    for (int i = 0; i < 8; ++i) {
        float* dst = &Out[(size_t)(m0 + ty * 8 + i) * C + n0 + tx * 4];
        *reinterpret_cast<float4*>(dst) =
            make_float4(acc[i][0], acc[i][1], acc[i][2], acc[i][3]);
        *reinterpret_cast<float4*>(dst + 64) =
            make_float4(acc[i][4], acc[i][5], acc[i][6], acc[i][7]);
    }
}

// ---------------- fat kernels: knn blocks + uv blocks in one launch --------
__global__ __launch_bounds__(256)
void fatL1(const float* __restrict__ x, const float* __restrict__ W1,
           int* __restrict__ idx, float* __restrict__ U, float* __restrict__ V) {
    extern __shared__ float sm[];
    const int bid = blockIdx.x;
    if (bid < 512) knn_body<8, true>(x, idx, bid, sm);
    else           uv1_body(x, W1, U, V, bid - 512, sm);
}

__global__ __launch_bounds__(256)
void fatL2(const float* __restrict__ h1, const float* __restrict__ W2,
           int* __restrict__ idx, float* __restrict__ U, float* __restrict__ V) {
    extern __shared__ float sm[];
    const int bid = blockIdx.x;
    if (bid < 512) knn_body<64, false>(h1, idx, bid, sm);
    else {
        const int b2 = bid - 512;                  // [0, 512)
        uv_body8<64>(h1, W2, 128, U, V, b2 & 255, b2 >> 8, sm);
    }
}

__global__ __launch_bounds__(256)
void fatL3(const float* __restrict__ h2, const float* __restrict__ W3,
           int* __restrict__ idx, float* __restrict__ U, float* __restrict__ V) {
    extern __shared__ float sm[];
    const int bid = blockIdx.x;
    if (bid < 512) knn_body<128, false>(h2, idx, bid, sm);
    else {
        const int b2 = bid - 512;                  // [0, 1024)
        uv_body8<128>(h2, W3, 256, U, V, b2 & 255, b2 >> 8, sm);
    }
}

// ---------------- neighbor aggregation + BN + ReLU (32-bit offsets) --------
template<int C>
__global__ __launch_bounds__(256)
void agg_kernel(const float* __restrict__ U, const float* __restrict__ V,
                const int* __restrict__ idx, const float* __restrict__ bias,
                const float* __restrict__ g, const float* __restrict__ be,
                float* __restrict__ H) {
    constexpr int PPB = 256 / C;
    __shared__ int sidx[PPB * KNBR];
    const int p0 = blockIdx.x * PPB;
    const int t = threadIdx.x;
    if (t < PPB * KNBR) sidx[t] = idx[(size_t)p0 * KNBR + t] * C;
    __syncthreads();
    const int lp = t / C, c = t % C;
    const int pt = p0 + lp;
    const int b = pt >> 8;
    const float* VbC = V + ((size_t)(b << 8)) * C + c;
    float u = U[(size_t)pt * C + c];
    float v = V[(size_t)pt * C + c];
    float mx = -INFINITY, mn = INFINITY;
    #pragma unroll
    for (int k = 0; k < KNBR; ++k) {
        float val = VbC[sidx[lp * KNBR + k]];
        mx = fmaxf(mx, val);
        mn = fminf(mn, val);
    }
    float a = g[c] * BN_SCALE_F;
    float m = (a >= 0.f) ? mx : mn;
    float h = fmaf(a, u - v + m + bias[c], be[c]);
    H[(size_t)pt * C + c] = fmaxf(h, 0.f);
}

// ------- layer-3 aggregation fused with global max pool (h >= 0) -----------
template<int C>
__global__ __launch_bounds__(256)
void agg_pool_kernel(const float* __restrict__ U, const float* __restrict__ V,
                     const int* __restrict__ idx, const float* __restrict__ bias,
                     const float* __restrict__ g, const float* __restrict__ be,
                     int* __restrict__ P) {
    __shared__ int sidx[KNBR];
    const int pt = blockIdx.x;
    const int t = threadIdx.x;
    if (t < KNBR) sidx[t] = idx[(size_t)pt * KNBR + t] * C;
    __syncthreads();
    const int c = t;
    const int b = pt >> 8;
    const float* VbC = V + ((size_t)(b << 8)) * C + c;
    float u = U[(size_t)pt * C + c];
    float v = V[(size_t)pt * C + c];
    float mx = -INFINITY, mn = INFINITY;
    #pragma unroll
    for (int k = 0; k < KNBR; ++k) {
        float val = VbC[sidx[k]];
        mx = fmaxf(mx, val);
        mn = fminf(mn, val);
    }
    float a = g[c] * BN_SCALE_F;
    float m = (a >= 0.f) ? mx : mn;
    float h = fmaxf(fmaf(a, u - v + m + bias[c], be[c]), 0.f);
    atomicMax(&P[b * C + c], __float_as_int(h));   // h >= 0: int cmp == float cmp
}

// ---------------- FC head --------------------------------------------------
__global__ __launch_bounds__(256)
void head_kernel(const float* __restrict__ Pp, const float* __restrict__ Wf1,
                 const float* __restrict__ bf1, const float* __restrict__ gf,
                 const float* __restrict__ bef, const float* __restrict__ Wf2,
                 const float* __restrict__ bf2, float* __restrict__ out) {
    __shared__ float ps[256];
    __shared__ float fs[128];
    const int b = blockIdx.x, t = threadIdx.x;
    ps[t] = Pp[b * 256 + t];
    __syncthreads();
    if (t < 128) {
        float acc = bf1[t];
        for (int r = 0; r < 256; ++r) acc += ps[r] * Wf1[r * 128 + t];
        float a = gf[t] * BN_SCALE_F;
        fs[t] = fmaxf(fmaf(a, acc, bef[t]), 0.f);
    }
    __syncthreads();
    if (t < 12) {
        float acc = bf2[t];
        for (int j = 0; j < 128; ++j) acc += fs[j] * Wf2[j * 12 + t];
        out[b * 12 + t] = acc;
    }
}

// ---------------- launch ----------------------------------------------------
extern "C" void kernel_launch(void* const* d_in, const int* in_sizes, int n_in,
                              void* d_out, int out_size) {
    const float* x   = (const float*)d_in[0];
    const float* W1  = (const float*)d_in[1];
    const float* b1  = (const float*)d_in[2];
    const float* g1  = (const float*)d_in[3];
    const float* be1 = (const float*)d_in[4];
    const float* W2  = (const float*)d_in[5];
    const float* b2  = (const float*)d_in[6];
    const float* g2  = (const float*)d_in[7];
    const float* be2 = (const float*)d_in[8];
    const float* W3  = (const float*)d_in[9];
    const float* b3  = (const float*)d_in[10];
    const float* g3  = (const float*)d_in[11];
    const float* be3 = (const float*)d_in[12];
    const float* Wf1 = (const float*)d_in[13];
    const float* bf1 = (const float*)d_in[14];
    const float* gf  = (const float*)d_in[15];
    const float* bef = (const float*)d_in[16];
    const float* Wf2 = (const float*)d_in[17];
    const float* bf2 = (const float*)d_in[18];
    float* out = (float*)d_out;

    float *U, *V, *h1, *h2, *p;
    int* idx;
    cudaGetSymbolAddress((void**)&U,  g_U);
    cudaGetSymbolAddress((void**)&V,  g_V);
    cudaGetSymbolAddress((void**)&h1, g_h1);
    cudaGetSymbolAddress((void**)&h2, g_h2);
    cudaGetSymbolAddress((void**)&idx, g_idx);
    cudaGetSymbolAddress((void**)&p,  g_p);

    cudaFuncSetAttribute(fatL1, cudaFuncAttributeMaxDynamicSharedMemorySize, FAT_SMEM_BYTES);
    cudaFuncSetAttribute(fatL2, cudaFuncAttributeMaxDynamicSharedMemorySize, FAT_SMEM_BYTES);
    cudaFuncSetAttribute(fatL3, cudaFuncAttributeMaxDynamicSharedMemorySize, FAT_SMEM_BYTES);

    // ---- layer 1: D=6 -> C=64 ----
    fatL1<<<512 + 1024, 256, FAT_SMEM_BYTES>>>(x, W1, idx, U, V);
    agg_kernel<64><<<MM / 4, 256>>>(U, V, idx, b1, g1, be1, h1);

    // ---- layer 2: D=64 -> C=128 ----
    fatL2<<<512 + 512, 256, FAT_SMEM_BYTES>>>(h1, W2, idx, U, V);
    agg_kernel<128><<<MM / 2, 256>>>(U, V, idx, b2, g2, be2, h2);

    // ---- layer 3: D=128 -> C=256 ----
    fatL3<<<512 + 1024, 256, FAT_SMEM_BYTES>>>(h2, W3, idx, U, V);
    cudaMemsetAsync(p, 0, BB * 256 * sizeof(float));
    agg_pool_kernel<256><<<MM, 256>>>(U, V, idx, b3, g3, be3, (int*)p);

    // ---- head ----
    head_kernel<<<BB, 256>>>(p, Wf1, bf1, gf, bef, Wf2, bf2, out);
}